// round 6
// baseline (speedup 1.0000x reference)
#include <cuda_runtime.h>

constexpr int NDRUG = 50000;
constexpr int NGENE = 50000;
constexpr int DHID  = 64;
constexpr int DEMB  = 32;
constexpr int EMAX  = 600000;

// Scratch (device globals — no allocation allowed)
__device__ float g_tm[2][NDRUG * 128];         // packed transformed features (per src type)
__device__ float g_h[2][NDRUG * DHID];         // hidden outputs (hd, hg)
__device__ float g_wp1[2][128 * 128];          // packed layer-1 weights
__device__ float g_wp2[2][64 * 64];            // packed layer-2 weights
__device__ int   g_deg[4 * NDRUG];
__device__ int   g_rowstart[4 * (NDRUG + 1)];
__device__ int   g_cursor[4 * (NDRUG + 1)];
__device__ int   g_csr[4 * EMAX];

struct Iptr4 { const int* p[4]; };
struct Ptr2  { const float* p[2]; };
struct Fptr2 { float* p[2]; };
struct PackAll {
    const float* w1[4];   // W1_dd, W1_dg, W1_gd, W1_gg
    const float* w2[4];
    float *wp1d, *wp1g, *wp2d, *wp2g;
};

// ---------------------------------------------------------------------------
// prep: y<4 -> degree histogram for relation y; y==4 -> pack all weights
// ---------------------------------------------------------------------------
__global__ void prep_kernel(Iptr4 dst, int* __restrict__ deg, int E, PackAll pa) {
    int y = blockIdx.y;
    int idx = blockIdx.x * blockDim.x + threadIdx.x;
    if (y < 4) {
        if (idx < E) atomicAdd(&deg[y * NDRUG + dst.p[y][idx]], 1);
        return;
    }
    // pack: region sizes 16384,16384,4096,4096 (flat indexing)
    // [W_a | W_b] : out[k][c] = c<N ? a[k*N+c] : b[k*N+c-N]
    if (idx < 16384) {                       // wp1d: K=128,N=64
        int c = idx & 127, k = idx >> 7;
        pa.wp1d[idx] = (c < 64) ? pa.w1[0][k * 64 + c] : pa.w1[1][k * 64 + c - 64];
    } else if (idx < 32768) {                // wp1g
        int j = idx - 16384;
        int c = j & 127, k = j >> 7;
        pa.wp1g[j] = (c < 64) ? pa.w1[2][k * 64 + c] : pa.w1[3][k * 64 + c - 64];
    } else if (idx < 36864) {                // wp2d: K=64,N=32
        int j = idx - 32768;
        int c = j & 63, k = j >> 6;
        pa.wp2d[j] = (c < 32) ? pa.w2[0][k * 32 + c] : pa.w2[1][k * 32 + c - 32];
    } else if (idx < 40960) {                // wp2g
        int j = idx - 36864;
        int c = j & 63, k = j >> 6;
        pa.wp2g[j] = (c < 32) ? pa.w2[2][k * 32 + c] : pa.w2[3][k * 32 + c - 32];
    }
}

// ---------------------------------------------------------------------------
// exclusive prefix scan of degrees -> rowstart AND cursor; 1 block/relation
// ---------------------------------------------------------------------------
__global__ __launch_bounds__(1024)
void scan4_kernel(const int* __restrict__ deg, int* __restrict__ rowstart,
                  int* __restrict__ cursor) {
    int r = blockIdx.x;
    const int* dg = deg + r * NDRUG;
    int* rs = rowstart + (size_t)r * (NDRUG + 1);
    int* cu = cursor   + (size_t)r * (NDRUG + 1);
    __shared__ int warpsum[32];
    __shared__ int carry_sh;
    int t = threadIdx.x, lane = t & 31, w = t >> 5;
    if (t == 0) carry_sh = 0;
    __syncthreads();
    for (int base = 0; base < NDRUG; base += 1024) {
        int idx = base + t;
        int v = (idx < NDRUG) ? dg[idx] : 0;
        int x = v;
#pragma unroll
        for (int off = 1; off < 32; off <<= 1) {
            int y = __shfl_up_sync(~0u, x, off);
            if (lane >= off) x += y;
        }
        if (lane == 31) warpsum[w] = x;
        __syncthreads();
        if (w == 0) {
            int s = warpsum[lane];
#pragma unroll
            for (int off = 1; off < 32; off <<= 1) {
                int y = __shfl_up_sync(~0u, s, off);
                if (lane >= off) s += y;
            }
            warpsum[lane] = s;
        }
        __syncthreads();
        int woff = (w > 0) ? warpsum[w - 1] : 0;
        int incl = x + woff;
        int carry = carry_sh;
        if (idx < NDRUG) { int val = carry + incl - v; rs[idx] = val; cu[idx] = val; }
        __syncthreads();
        if (t == 1023) carry_sh = carry + incl;
        __syncthreads();
    }
    if (t == 0) { rs[NDRUG] = carry_sh; cu[NDRUG] = carry_sh; }
}

// ---------------------------------------------------------------------------
// MEGA kernel: blocks [0, 2*gblk) do layer-1 packed GEMM (K=128, N=128),
// blocks [2*gblk, ...) do CSR fill. Both 256 threads.
// ---------------------------------------------------------------------------
__global__ __launch_bounds__(256, 2)
void mega1_kernel(Ptr2 Xa, Ptr2 Wa, Fptr2 Ya, int M, int gblk,
                  Iptr4 src, Iptr4 dst, int* __restrict__ cursor,
                  int* __restrict__ csr, int E, int fillBlocksPerRel) {
    constexpr int K = 128, N = 128;
    constexpr int BM = 128, BK = 16, TM = 8, TN = 8;
    const int tid = threadIdx.x;
    const int gemmBlocks = 2 * gblk;

    if ((int)blockIdx.x >= gemmBlocks) {
        // ---- CSR fill path ----
        int fidx = blockIdx.x - gemmBlocks;
        int r = fidx / fillBlocksPerRel;
        int i = (fidx % fillBlocksPerRel) * 256 + tid;
        if (i < E) {
            int d = dst.p[r][i];
            int pos = atomicAdd(&cursor[(size_t)r * (NDRUG + 1) + d], 1);
            csr[(size_t)r * EMAX + pos] = src.p[r][i];
        }
        return;
    }

    // ---- GEMM path ----
    const int y  = blockIdx.x / gblk;
    const int bx = blockIdx.x % gblk;
    const float* __restrict__ X = Xa.p[y];
    const float* __restrict__ W = Wa.p[y];
    float* __restrict__ Y = Ya.p[y];

    __shared__ float Xs[BK][BM + 4];
    __shared__ float Ws[BK][N + 4];

    const int trow = tid / 16;          // 0..15
    const int tcol = tid % 16;
    const int m0   = bx * BM;

    float acc[TM][TN];
#pragma unroll
    for (int i = 0; i < TM; i++)
#pragma unroll
        for (int j = 0; j < TN; j++) acc[i][j] = 0.f;

    for (int k0 = 0; k0 < K; k0 += BK) {
        constexpr int XF4 = BM * BK / 4;       // 512 float4
#pragma unroll
        for (int it = 0; it < XF4 / 256; it++) {
            int lin = tid + it * 256;
            int row = lin >> 2;
            int kk  = (lin & 3) * 4;
            int gr  = m0 + row;
            float4 v = make_float4(0.f, 0.f, 0.f, 0.f);
            if (gr < M) v = *(const float4*)(X + (size_t)gr * K + k0 + kk);
            Xs[kk + 0][row] = v.x; Xs[kk + 1][row] = v.y;
            Xs[kk + 2][row] = v.z; Xs[kk + 3][row] = v.w;
        }
        constexpr int WF4 = BK * N / 4;
#pragma unroll
        for (int it = 0; it < WF4 / 256; it++) {
            int lin = tid + it * 256;
            int row = lin / (N / 4);
            int c4  = (lin % (N / 4)) * 4;
            float4 v = *(const float4*)(W + (size_t)(k0 + row) * N + c4);
            Ws[row][c4 + 0] = v.x; Ws[row][c4 + 1] = v.y;
            Ws[row][c4 + 2] = v.z; Ws[row][c4 + 3] = v.w;
        }
        __syncthreads();
#pragma unroll
        for (int k = 0; k < BK; k++) {
            float4 a0 = *(const float4*)&Xs[k][trow * TM];
            float4 a1 = *(const float4*)&Xs[k][trow * TM + 4];
            float4 b0 = *(const float4*)&Ws[k][tcol * TN];
            float4 b1 = *(const float4*)&Ws[k][tcol * TN + 4];
            float a[TM] = {a0.x, a0.y, a0.z, a0.w, a1.x, a1.y, a1.z, a1.w};
            float b[TN] = {b0.x, b0.y, b0.z, b0.w, b1.x, b1.y, b1.z, b1.w};
#pragma unroll
            for (int i = 0; i < TM; i++)
#pragma unroll
                for (int j = 0; j < TN; j++) acc[i][j] += a[i] * b[j];
        }
        __syncthreads();
    }
#pragma unroll
    for (int i = 0; i < TM; i++) {
        int gr = m0 + trow * TM + i;
        if (gr < M) {
            *(float4*)(Y + (size_t)gr * N + tcol * TN)     =
                make_float4(acc[i][0], acc[i][1], acc[i][2], acc[i][3]);
            *(float4*)(Y + (size_t)gr * N + tcol * TN + 4) =
                make_float4(acc[i][4], acc[i][5], acc[i][6], acc[i][7]);
        }
    }
}

// ---------------------------------------------------------------------------
// Layer-2 packed GEMM (K=64, N=64), gridDim.y = 2
// ---------------------------------------------------------------------------
template<int K, int N>
__launch_bounds__((N / 8) * 16, 2)
__global__ void gemmp_kernel(Ptr2 Xa, Ptr2 Wa, Fptr2 Ya, int M) {
    constexpr int BM = 128, BK = 16, TM = 8, TN = 8;
    constexpr int TCOLS = N / TN;
    constexpr int THREADS = (BM / TM) * TCOLS;
    const int y = blockIdx.y;
    const float* __restrict__ X = Xa.p[y];
    const float* __restrict__ W = Wa.p[y];
    float* __restrict__ Y = Ya.p[y];

    __shared__ float Xs[BK][BM + 4];
    __shared__ float Ws[BK][N + 4];

    const int tid  = threadIdx.x;
    const int trow = tid / TCOLS;
    const int tcol = tid % TCOLS;
    const int m0   = blockIdx.x * BM;

    float acc[TM][TN];
#pragma unroll
    for (int i = 0; i < TM; i++)
#pragma unroll
        for (int j = 0; j < TN; j++) acc[i][j] = 0.f;

    for (int k0 = 0; k0 < K; k0 += BK) {
        constexpr int XF4 = BM * BK / 4;
#pragma unroll
        for (int it = 0; it < XF4 / THREADS; it++) {
            int lin = tid + it * THREADS;
            int row = lin >> 2;
            int kk  = (lin & 3) * 4;
            int gr  = m0 + row;
            float4 v = make_float4(0.f, 0.f, 0.f, 0.f);
            if (gr < M) v = *(const float4*)(X + (size_t)gr * K + k0 + kk);
            Xs[kk + 0][row] = v.x; Xs[kk + 1][row] = v.y;
            Xs[kk + 2][row] = v.z; Xs[kk + 3][row] = v.w;
        }
        constexpr int WF4 = BK * N / 4;
#pragma unroll
        for (int it = 0; it < WF4 / THREADS; it++) {
            int lin = tid + it * THREADS;
            int row = lin / (N / 4);
            int c4  = (lin % (N / 4)) * 4;
            float4 v = *(const float4*)(W + (size_t)(k0 + row) * N + c4);
            Ws[row][c4 + 0] = v.x; Ws[row][c4 + 1] = v.y;
            Ws[row][c4 + 2] = v.z; Ws[row][c4 + 3] = v.w;
        }
        __syncthreads();
#pragma unroll
        for (int k = 0; k < BK; k++) {
            float4 a0 = *(const float4*)&Xs[k][trow * TM];
            float4 a1 = *(const float4*)&Xs[k][trow * TM + 4];
            float4 b0 = *(const float4*)&Ws[k][tcol * TN];
            float4 b1 = *(const float4*)&Ws[k][tcol * TN + 4];
            float a[TM] = {a0.x, a0.y, a0.z, a0.w, a1.x, a1.y, a1.z, a1.w};
            float b[TN] = {b0.x, b0.y, b0.z, b0.w, b1.x, b1.y, b1.z, b1.w};
#pragma unroll
            for (int i = 0; i < TM; i++)
#pragma unroll
                for (int j = 0; j < TN; j++) acc[i][j] += a[i] * b[j];
        }
        __syncthreads();
    }
#pragma unroll
    for (int i = 0; i < TM; i++) {
        int gr = m0 + trow * TM + i;
        if (gr < M) {
            *(float4*)(Y + (size_t)gr * N + tcol * TN)     =
                make_float4(acc[i][0], acc[i][1], acc[i][2], acc[i][3]);
            *(float4*)(Y + (size_t)gr * N + tcol * TN + 4) =
                make_float4(acc[i][4], acc[i][5], acc[i][6], acc[i][7]);
        }
    }
}

// ---------------------------------------------------------------------------
// Fused dual gather: gridDim.y selects (drug | gene) config.
// ---------------------------------------------------------------------------
struct GatherCfg {
    const float* tmA; const int* csrA; const int* rsA;
    const float* tmB; const int* csrB; const int* rsB;
    const float* bias; float* out;
};

template<int D, int LD, bool RELU>
__launch_bounds__(256)
__global__ void gather_dual_kernel(GatherCfg c0, GatherCfg c1, int n) {
    constexpr int V = D / 32;
    const GatherCfg c = blockIdx.y ? c1 : c0;
    int warp = (blockIdx.x * blockDim.x + threadIdx.x) >> 5;
    int lane = threadIdx.x & 31;
    if (warp >= n) return;

    float res[V];
#pragma unroll
    for (int j = 0; j < V; j++) res[j] = c.bias[lane * V + j];

#pragma unroll
    for (int rel = 0; rel < 2; rel++) {
        const float* tm  = rel ? c.tmB  : c.tmA;
        const int*   csr = rel ? c.csrB : c.csrA;
        const int*   rs  = rel ? c.rsB  : c.rsA;
        int s = rs[warp], e = rs[warp + 1];
        float inv = 1.0f / (float)max(e - s, 1);
        float acc[V];
#pragma unroll
        for (int j = 0; j < V; j++) acc[j] = 0.f;
        int i = s;
        for (; i + 4 <= e; i += 4) {
            int s0 = csr[i], s1 = csr[i + 1], s2 = csr[i + 2], s3 = csr[i + 3];
            if (V == 2) {
                float2 v0 = ((const float2*)(tm + (size_t)s0 * LD))[lane];
                float2 v1 = ((const float2*)(tm + (size_t)s1 * LD))[lane];
                float2 v2 = ((const float2*)(tm + (size_t)s2 * LD))[lane];
                float2 v3 = ((const float2*)(tm + (size_t)s3 * LD))[lane];
                acc[0] += (v0.x + v1.x) + (v2.x + v3.x);
                acc[1] += (v0.y + v1.y) + (v2.y + v3.y);
            } else {
                float v0 = tm[(size_t)s0 * LD + lane];
                float v1 = tm[(size_t)s1 * LD + lane];
                float v2 = tm[(size_t)s2 * LD + lane];
                float v3 = tm[(size_t)s3 * LD + lane];
                acc[0] += (v0 + v1) + (v2 + v3);
            }
        }
        for (; i < e; i++) {
            int s0 = csr[i];
            if (V == 2) {
                float2 v0 = ((const float2*)(tm + (size_t)s0 * LD))[lane];
                acc[0] += v0.x; acc[1] += v0.y;
            } else {
                acc[0] += tm[(size_t)s0 * LD + lane];
            }
        }
#pragma unroll
        for (int j = 0; j < V; j++) res[j] += acc[j] * inv;
    }

    if (RELU) {
#pragma unroll
        for (int j = 0; j < V; j++) res[j] = fmaxf(res[j], 0.f);
    }
    if (V == 2) {
        ((float2*)(c.out + (size_t)warp * D))[lane] = make_float2(res[0], res[1]);
    } else {
        c.out[(size_t)warp * D + lane] = res[0];
    }
}

// ---------------------------------------------------------------------------
// Orchestration
// ---------------------------------------------------------------------------
extern "C" void kernel_launch(void* const* d_in, const int* in_sizes, int n_in,
                              void* d_out, int out_size) {
    const float* xd = (const float*)d_in[0];
    const float* xg = (const float*)d_in[1];
    const int* es[8];
    for (int i = 0; i < 8; i++) es[i] = (const int*)d_in[2 + i];
    const float* W1[4] = {(const float*)d_in[10], (const float*)d_in[11],
                          (const float*)d_in[12], (const float*)d_in[13]};
    const float* b1d = (const float*)d_in[14];
    const float* b1g = (const float*)d_in[15];
    const float* W2[4] = {(const float*)d_in[16], (const float*)d_in[17],
                          (const float*)d_in[18], (const float*)d_in[19]};
    const float* b2d = (const float*)d_in[20];
    const float* b2g = (const float*)d_in[21];
    float* out = (float*)d_out;
    const int E = in_sizes[2];

    float *tm, *h, *wp1, *wp2;
    int *deg, *rowstart, *cursor, *csr;
    cudaGetSymbolAddress((void**)&tm,       g_tm);
    cudaGetSymbolAddress((void**)&h,        g_h);
    cudaGetSymbolAddress((void**)&wp1,      g_wp1);
    cudaGetSymbolAddress((void**)&wp2,      g_wp2);
    cudaGetSymbolAddress((void**)&deg,      g_deg);
    cudaGetSymbolAddress((void**)&rowstart, g_rowstart);
    cudaGetSymbolAddress((void**)&cursor,   g_cursor);
    cudaGetSymbolAddress((void**)&csr,      g_csr);

    const int TB = 256;
    const int gblk = (NDRUG + 127) / 128;           // 391
    const int fillBlocksPerRel = (E + TB - 1) / TB; // 2344

    Iptr4 srcs = {{es[0], es[2], es[4], es[6]}};
    Iptr4 dsts = {{es[1], es[3], es[5], es[7]}};

    float* tm0 = tm;
    float* tm1 = tm + (size_t)NDRUG * 128;
    float* wp1d = wp1;                 float* wp1g = wp1 + 128 * 128;
    float* wp2d = wp2;                 float* wp2g = wp2 + 64 * 64;

    // --- prep: degrees + weight packing (one launch) ---
    cudaMemsetAsync(deg, 0, sizeof(int) * 4 * NDRUG, 0);
    PackAll pa;
    for (int i = 0; i < 4; i++) { pa.w1[i] = W1[i]; pa.w2[i] = W2[i]; }
    pa.wp1d = wp1d; pa.wp1g = wp1g; pa.wp2d = wp2d; pa.wp2g = wp2g;
    prep_kernel<<<dim3(fillBlocksPerRel, 5), TB>>>(dsts, deg, E, pa);

    // --- scan (writes rowstart + cursor) ---
    scan4_kernel<<<4, 1024>>>(deg, rowstart, cursor);

    const int* rs[4] = {rowstart, rowstart + (NDRUG + 1),
                        rowstart + 2 * (NDRUG + 1), rowstart + 3 * (NDRUG + 1)};
    const int* cs[4] = {csr, csr + EMAX, csr + 2 * (size_t)EMAX, csr + 3 * (size_t)EMAX};

    // --- MEGA: layer-1 GEMM (both src types) + CSR fill, one launch ---
    {
        Ptr2  X = {{xd, xg}};
        Ptr2  W = {{wp1d, wp1g}};
        Fptr2 Y = {{tm0, tm1}};
        int totalBlocks = 2 * gblk + 4 * fillBlocksPerRel;
        mega1_kernel<<<totalBlocks, TB>>>(X, W, Y, NDRUG, gblk,
                                          srcs, dsts, cursor, csr, E, fillBlocksPerRel);
    }

    int gather_blocks = (NDRUG * 32 + TB - 1) / TB;

    // --- layer-1 gather ---
    {
        GatherCfg cd = {tm0,      cs[0], rs[0], tm1,      cs[2], rs[2], b1d, h};
        GatherCfg cg = {tm0 + 64, cs[1], rs[1], tm1 + 64, cs[3], rs[3], b1g,
                        h + (size_t)NDRUG * DHID};
        gather_dual_kernel<64, 128, true><<<dim3(gather_blocks, 2), TB>>>(cd, cg, NDRUG);
    }

    // --- layer 2 ---
    {
        const float* hd = h;
        const float* hg = h + (size_t)NDRUG * DHID;
        Ptr2  X = {{hd, hg}};
        Ptr2  W = {{wp2d, wp2g}};
        Fptr2 Y = {{tm0, tm1}};
        gemmp_kernel<64, 64><<<dim3(gblk, 2), 128>>>(X, W, Y, NDRUG);

        GatherCfg cd = {tm0,      cs[0], rs[0], tm1,      cs[2], rs[2], b2d, out};
        GatherCfg cg = {tm0 + 32, cs[1], rs[1], tm1 + 32, cs[3], rs[3], b2g,
                        out + (size_t)NDRUG * DEMB};
        gather_dual_kernel<32, 64, false><<<dim3(gather_blocks, 2), TB>>>(cd, cg, NDRUG);
    }
}